// round 13
// baseline (speedup 1.0000x reference)
#include <cuda_runtime.h>
#include <math.h>
#include <string.h>

#define HDIM   256
#define NCELL  32
#define DTH    31
#define EPSF   1e-7f
#define TINYF  1e-10f
#define GTAB   1024                  // table cells; nodes = GTAB+1
#define KCH    32                    // k-chunks for u,c partial reduction
#define NB_A   32                    // role-A blocks (k0u partials)
#define NB_B   132                   // role-B blocks (kT1: 33 groups x 4 j)
#define NB_C   33                    // role-C blocks (kT2)

// ---------------- device scratch (no cudaMalloc allowed) ----------------
__device__ float g_upart[KCH * HDIM];       // partial sums of u
__device__ float g_cpart[KCH * HDIM];       // partial sums of c (pre-b1)
__device__ float g_H2[(GTAB + 64) * HDIM];  // h2 table (+pad rows; unwritten rows stay 0)
__device__ float g_Atab[(GTAB + 2) * 64];   // A table rows
__device__ unsigned int g_sync[1 + NB_C];   // [0]=A-done count; [1+g]=B-done per group

struct BParam { float B[DTH * 64]; };       // 7936 B kernel param

// ============================================================================
// Host: numpy SVD null-space basis B = Vt[33:].T via Householder LQ
// (dgesdd Path 4t: dgelqf + dorglq). Input-independent -> host fp64.
// ============================================================================
static void compute_basis_host(float* Bout /* [DTH][64] */)
{
    static double L[33][64];
    static double Bm[DTH][64];
    static double tau[33];
    memset(L, 0, sizeof(L));
    memset(Bm, 0, sizeof(Bm));

    for (int i = 1; i < NCELL; i++) {
        double xi = (double)i / (double)NCELL;
        L[i - 1][2 * (i - 1)]     = xi;
        L[i - 1][2 * (i - 1) + 1] = 1.0;
        L[i - 1][2 * i]           = -xi;
        L[i - 1][2 * i + 1]       = -1.0;
    }
    L[NCELL - 1][1]               = 1.0;
    L[NCELL][2 * (NCELL - 1)]     = 1.0;
    L[NCELL][2 * (NCELL - 1) + 1] = 1.0;

    for (int i = 0; i < 33; i++) {
        double xn2 = 0.0;
        for (int j = i + 1; j < 64; j++) xn2 += L[i][j] * L[i][j];
        if (xn2 == 0.0) { tau[i] = 0.0; continue; }
        double alpha = L[i][i];
        double beta = sqrt(alpha * alpha + xn2);
        beta = (alpha >= 0.0) ? -beta : beta;
        tau[i] = (beta - alpha) / beta;
        double sc = 1.0 / (alpha - beta);
        for (int j = i + 1; j < 64; j++) L[i][j] *= sc;
        L[i][i] = beta;
        for (int r = i + 1; r < 33; r++) {
            double w = L[r][i];
            for (int j = i + 1; j < 64; j++) w += L[r][j] * L[i][j];
            w *= tau[i];
            L[r][i] -= w;
            for (int j = i + 1; j < 64; j++) L[r][j] -= w * L[i][j];
        }
    }
    for (int r = 0; r < DTH; r++) Bm[r][33 + r] = 1.0;
    for (int i = 32; i >= 0; i--) {
        if (tau[i] == 0.0) continue;
        for (int r = 0; r < DTH; r++) {
            double w = Bm[r][i];
            for (int j = i + 1; j < 64; j++) w += Bm[r][j] * L[i][j];
            w *= tau[i];
            Bm[r][i] -= w;
            for (int j = i + 1; j < 64; j++) Bm[r][j] -= w * L[i][j];
        }
    }
    for (int d = 0; d < DTH; d++)
        for (int j = 0; j < 64; j++)
            Bout[d * 64 + j] = (float)Bm[d][j];
}

// ---------------- shared-memory union for the fused roles ----------------
struct T1S {
    float us[HDIM], cs[HDIM], xs[32];
    float As[16][36];
    float Bs[16][64];
};
struct T2S {
    float H2s[256][33];
    float Ts[32][33];
    float Bb[DTH][64];
};
union SMU { T1S t1; T2S t2; };

// ============================================================================
// kFused: producer chain in ONE kernel with flag-based pipelining.
//   Role A (blocks 0..31):    u,c partials (k0u).
//   Role B (blocks 32..163):  kT1 GEMM tiles; spin on g_sync[0]==NB_A.
//   Role C (blocks 164..196): kT2 projection; spin on g_sync[1+g]==4.
// All 197 blocks co-resident (46KB smem -> 4 blocks/SM x 148 = 592 slots),
// so spin waits cannot deadlock. Counters pre-zeroed by a memset node.
// ============================================================================
__global__ void __launch_bounds__(256) kFused(
    const float* __restrict__ w0, const float* __restrict__ b0,
    const float* __restrict__ w1, const float* __restrict__ b1,
    const float* __restrict__ w2, const float* __restrict__ b2,
    const BParam Bp,
    const float* __restrict__ w3, const float* __restrict__ b3, int nrows)
{
    __shared__ SMU smu;
    const int bx = blockIdx.x;
    const int tid = threadIdx.x;

    if (bx < NB_A) {
        // ---------------- Role A: u,c partials ----------------
        float uu = 0.f, cc = 0.f;
#pragma unroll
        for (int kk = 0; kk < HDIM / KCH; kk++) {
            int k = bx * (HDIM / KCH) + kk;
            float wv = w1[k * HDIM + tid];
            uu = fmaf(w0[k], wv, uu);
            cc = fmaf(b0[k], wv, cc);
        }
        g_upart[bx * HDIM + tid] = uu;
        g_cpart[bx * HDIM + tid] = cc;
        __threadfence();
        __syncthreads();
        if (tid == 0) atomicAdd(&g_sync[0], 1u);
        return;
    }

    if (bx < NB_A + NB_B) {
        // ---------------- Role B: kT1 GEMM tile ----------------
        const int idx = bx - NB_A;
        const int grp = idx >> 2;            // row group 0..32
        const int jy  = idx & 3;             // j block 0..3
        const int i0 = grp * 32;
        const int j0 = jy * 64;

        if (tid == 0) {
            while (atomicAdd(&g_sync[0], 0u) < (unsigned)NB_A) { }
            __threadfence();
        }
        __syncthreads();

        {
            float uu = 0.f, cc = 0.f;
#pragma unroll
            for (int b = 0; b < KCH; b++) {
                uu += g_upart[b * HDIM + tid];
                cc += g_cpart[b * HDIM + tid];
            }
            smu.t1.us[tid] = uu;
            smu.t1.cs[tid] = cc + b1[tid];
        }
        if (tid < 32)
            smu.t1.xs[tid] = (float)(i0 + tid) * (1.0f / (float)GTAB);
        __syncthreads();

        const int tx = tid & 31;
        const int ty = tid >> 5;

        float acc[4][2];
#pragma unroll
        for (int m = 0; m < 4; m++) { acc[m][0] = 0.f; acc[m][1] = 0.f; }

        for (int k0 = 0; k0 < HDIM; k0 += 16) {
#pragma unroll
            for (int s = 0; s < 2; s++) {
                int e = tid + s * 256;
                int kk = e >> 5, ii = e & 31;
                smu.t1.As[kk][ii] =
                    fmaxf(fmaf(smu.t1.xs[ii], smu.t1.us[k0 + kk], smu.t1.cs[k0 + kk]), 0.f);
            }
#pragma unroll
            for (int s = 0; s < 4; s++) {
                int e = tid + s * 256;
                int kk = e >> 6, jj = e & 63;
                smu.t1.Bs[kk][jj] = w2[(k0 + kk) * HDIM + j0 + jj];
            }
            __syncthreads();
#pragma unroll
            for (int kk = 0; kk < 16; kk++) {
                float4 a4 = *reinterpret_cast<const float4*>(&smu.t1.As[kk][ty * 4]);
                float2 bv = *reinterpret_cast<const float2*>(&smu.t1.Bs[kk][tx * 2]);
                float a[4] = {a4.x, a4.y, a4.z, a4.w};
#pragma unroll
                for (int m = 0; m < 4; m++) {
                    acc[m][0] = fmaf(a[m], bv.x, acc[m][0]);
                    acc[m][1] = fmaf(a[m], bv.y, acc[m][1]);
                }
            }
            __syncthreads();
        }

        float bb0 = b2[j0 + tx * 2];
        float bb1 = b2[j0 + tx * 2 + 1];
#pragma unroll
        for (int m = 0; m < 4; m++) {
            int row = i0 + ty * 4 + m;
            if (row < nrows) {
                float2 v;
                v.x = fmaxf(acc[m][0] + bb0, 0.f);
                v.y = fmaxf(acc[m][1] + bb1, 0.f);
                *reinterpret_cast<float2*>(&g_H2[row * HDIM + j0 + tx * 2]) = v;
            }
        }
        __threadfence();
        __syncthreads();
        if (tid == 0) atomicAdd(&g_sync[1 + grp], 1u);
        return;
    }

    // ---------------- Role C: kT2 projection ----------------
    {
        const int grp = bx - NB_A - NB_B;    // 0..32
        const int i0 = grp * 32;

        if (tid == 0) {
            while (atomicAdd(&g_sync[1 + grp], 0u) < 4u) { }
            __threadfence();
        }
        __syncthreads();

#pragma unroll
        for (int s = 0; s < 8; s++) {
            int e = tid + s * 256;           // 0..2047 float4 units
            int i = e >> 6, kq = e & 63;
            float4 v = *reinterpret_cast<const float4*>(&g_H2[(i0 + i) * HDIM + kq * 4]);
            smu.t2.H2s[kq * 4 + 0][i] = v.x;
            smu.t2.H2s[kq * 4 + 1][i] = v.y;
            smu.t2.H2s[kq * 4 + 2][i] = v.z;
            smu.t2.H2s[kq * 4 + 3][i] = v.w;
        }
        for (int e = tid; e < DTH * 64; e += 256)
            smu.t2.Bb[e >> 6][e & 63] = Bp.B[e];
        __syncthreads();

        // T = H2 @ w3 (+ b3)
        {
            const int i = tid & 31;
            const int dbase = (tid >> 5) * 4;
            float acc[4] = {0.f, 0.f, 0.f, 0.f};
#pragma unroll 4
            for (int k = 0; k < HDIM; k++) {
                float h = smu.t2.H2s[k][i];
#pragma unroll
                for (int q = 0; q < 4; q++) {
                    int d = dbase + q;
                    if (d < DTH)
                        acc[q] = fmaf(h, __ldg(&w3[k * DTH + d]), acc[q]);
                }
            }
#pragma unroll
            for (int q = 0; q < 4; q++) {
                int d = dbase + q;
                if (d < DTH) smu.t2.Ts[d][i] = acc[q] + b3[d];
            }
        }
        __syncthreads();

        // A = T @ B^T
        {
            const int j = tid & 63;
            const int ig = tid >> 6;
            float acc8[8];
#pragma unroll
            for (int m = 0; m < 8; m++) acc8[m] = 0.f;
#pragma unroll
            for (int d = 0; d < DTH; d++) {
                float bv = smu.t2.Bb[d][j];
#pragma unroll
                for (int m = 0; m < 8; m++)
                    acc8[m] = fmaf(smu.t2.Ts[d][ig + m * 4], bv, acc8[m]);
            }
#pragma unroll
            for (int m = 0; m < 8; m++) {
                int row = i0 + ig + m * 4;
                if (row < nrows)
                    g_Atab[row * 64 + j] = acc8[m];
            }
        }
    }
}

// ============================================================================
// k3: CPAB integration, 1 point/thread. Fast intrinsics throughout (incl.
//     e = b/a via __fdividef — table error dominates the budget by ~150x).
//     Exact fixpoint early-exit; clamps proven redundant removed.
// ============================================================================
__global__ void __launch_bounds__(256) k3_integrate(const float* __restrict__ x,
                                                    float* __restrict__ out, int n)
{
    const int ip = blockIdx.x * 256 + threadIdx.x;
    if (ip >= n) return;

    float2 xv = *reinterpret_cast<const float2*>(&x[2 * ip]);
    float x1 = fminf(fmaxf(xv.y, EPSF), 1.0f - EPSF);
    float f = x1 * (float)GTAB;
    int r = (int)f;                                  // in [0, GTAB-1] by range
    float fr = f - (float)r;
    const float2* row0 = reinterpret_cast<const float2*>(&g_Atab[r * 64]);
    const float2* row1 = reinterpret_cast<const float2*>(&g_Atab[(r + 1) * 64]);

    float xc = fminf(fmaxf(xv.x, EPSF), 1.0f - EPSF);
    float t = 1.0f;
    float S = 0.0f;
    const float inv = 1.0f / (float)NCELL;
    const float INF = __int_as_float(0x7f800000);

#pragma unroll 1
    for (int it = 0; it < NCELL + 2; it++) {
        int c = (int)(xc * (float)NCELL);            // in [0, 31] by range
        float2 p0 = __ldg(&row0[c]);
        float2 p1 = __ldg(&row1[c]);
        float a = fmaf(fr, p1.x - p0.x, p0.x);
        float b = fmaf(fr, p1.y - p0.y, p0.y);
        float v = a * xc + b;
        float xbnd = ((v >= 0.f) ? (float)(c + 1) : (float)c) * inv;
        bool  small_a = fabsf(a) < TINYF;
        float safe_a = small_a ? 1.0f : a;
        float e = __fdividef(b, safe_a);
        float denom = xc + e;
        float safe_denom = (fabsf(denom) < TINYF) ? ((denom >= 0.f) ? TINYF : -TINYF) : denom;
        float ratio = __fdividef(xbnd + e, safe_denom);
        float thit_exp = __fdividef(__logf(fmaxf(ratio, TINYF)), safe_a);
        float safe_b = (fabsf(b) < TINYF) ? TINYF : b;
        float thit_lin = __fdividef(xbnd - xc, safe_b);
        float thit = small_a ? thit_lin : ((ratio > TINYF) ? thit_exp : INF);
        thit = (thit <= 0.f) ? INF : thit;
        float dt = fminf(thit, t);
        bool cross = (thit <= t);
        float x_exp = (xc + e) * __expf(a * dt) - e;
        float x_lin = xc + b * dt;
        float xn = small_a ? x_lin : x_exp;
        float nudge = (v >= 0.f) ? 1e-7f : -1e-7f;
        xn = cross ? (xbnd + nudge) : xn;
        xn = fminf(fmaxf(xn, EPSF), 1.0f - EPSF);
        S += a * dt;
        t = t - dt;
        bool done = (dt == 0.0f) && (xn == xc);     // exact fixpoint
        xc = xn;
        if (__all_sync(0xffffffffu, done)) break;
    }

    float2 z; z.x = xc; z.y = x1;
    *reinterpret_cast<float2*>(&out[2 * ip]) = z;
    float2 g; g.x = S; g.y = 0.0f;
    *reinterpret_cast<float2*>(&out[2 * n + 2 * ip]) = g;
}

// ============================================================================
static BParam s_Bp;               // persists across graph replays

extern "C" void kernel_launch(void* const* d_in, const int* in_sizes, int n_in,
                              void* d_out, int out_size)
{
    const float* x  = (const float*)d_in[0];
    const float* w0 = (const float*)d_in[1];
    const float* b0 = (const float*)d_in[2];
    const float* w1 = (const float*)d_in[3];
    const float* b1 = (const float*)d_in[4];
    const float* w2 = (const float*)d_in[5];
    const float* b2 = (const float*)d_in[6];
    const float* w3 = (const float*)d_in[7];
    const float* b3 = (const float*)d_in[8];
    float* out = (float*)d_out;

    int n = in_sizes[0] / 2;
    const int nrows = GTAB + 1;

    compute_basis_host(s_Bp.B);     // input-independent, deterministic

    // zero sync counters (graph-legal memset node; no allocation)
    void* syncPtr = nullptr;
    cudaGetSymbolAddress(&syncPtr, g_sync);
    cudaMemsetAsync(syncPtr, 0, sizeof(unsigned int) * (1 + NB_C), 0);

    kFused<<<NB_A + NB_B + NB_C, 256>>>(w0, b0, w1, b1, w2, b2, s_Bp, w3, b3, nrows);

    k3_integrate<<<(n + 255) / 256, 256>>>(x, out, n);
}

// round 14
// speedup vs baseline: 1.2940x; 1.2940x over previous
#include <cuda_runtime.h>
#include <math.h>
#include <string.h>

#define HDIM   256
#define NCELL  32
#define DTH    31
#define EPSF   1e-7f
#define TINYF  1e-10f
#define GTAB   1024                  // table cells; nodes = GTAB+1
#define KCH    32                    // k-chunks for u,c partial reduction
#define NGRP   33                    // row groups of 32 (covers GTAB+1 rows)

// ---------------- device scratch (no cudaMalloc allowed) ----------------
__device__ float g_upart[KCH * HDIM];          // partial sums of u
__device__ float g_cpart[KCH * HDIM];          // partial sums of c (pre-b1)
__device__ float g_Tpart[NGRP * 4 * 32 * DTH]; // per-(grp,jy) w3 projections
__device__ float g_Atab[(GTAB + 2) * 64];      // A table rows

struct BParam { float B[DTH * 64]; };          // 7936 B kernel param

// ============================================================================
// Host: numpy SVD null-space basis B = Vt[33:].T via Householder LQ
// (dgesdd Path 4t: dgelqf + dorglq). Input-independent -> host fp64.
// ============================================================================
static void compute_basis_host(float* Bout /* [DTH][64] */)
{
    static double L[33][64];
    static double Bm[DTH][64];
    static double tau[33];
    memset(L, 0, sizeof(L));
    memset(Bm, 0, sizeof(Bm));

    for (int i = 1; i < NCELL; i++) {
        double xi = (double)i / (double)NCELL;
        L[i - 1][2 * (i - 1)]     = xi;
        L[i - 1][2 * (i - 1) + 1] = 1.0;
        L[i - 1][2 * i]           = -xi;
        L[i - 1][2 * i + 1]       = -1.0;
    }
    L[NCELL - 1][1]               = 1.0;
    L[NCELL][2 * (NCELL - 1)]     = 1.0;
    L[NCELL][2 * (NCELL - 1) + 1] = 1.0;

    for (int i = 0; i < 33; i++) {
        double xn2 = 0.0;
        for (int j = i + 1; j < 64; j++) xn2 += L[i][j] * L[i][j];
        if (xn2 == 0.0) { tau[i] = 0.0; continue; }
        double alpha = L[i][i];
        double beta = sqrt(alpha * alpha + xn2);
        beta = (alpha >= 0.0) ? -beta : beta;
        tau[i] = (beta - alpha) / beta;
        double sc = 1.0 / (alpha - beta);
        for (int j = i + 1; j < 64; j++) L[i][j] *= sc;
        L[i][i] = beta;
        for (int r = i + 1; r < 33; r++) {
            double w = L[r][i];
            for (int j = i + 1; j < 64; j++) w += L[r][j] * L[i][j];
            w *= tau[i];
            L[r][i] -= w;
            for (int j = i + 1; j < 64; j++) L[r][j] -= w * L[i][j];
        }
    }
    for (int r = 0; r < DTH; r++) Bm[r][33 + r] = 1.0;
    for (int i = 32; i >= 0; i--) {
        if (tau[i] == 0.0) continue;
        for (int r = 0; r < DTH; r++) {
            double w = Bm[r][i];
            for (int j = i + 1; j < 64; j++) w += Bm[r][j] * L[i][j];
            w *= tau[i];
            Bm[r][i] -= w;
            for (int j = i + 1; j < 64; j++) Bm[r][j] -= w * L[i][j];
        }
    }
    for (int d = 0; d < DTH; d++)
        for (int j = 0; j < 64; j++)
            Bout[d * 64 + j] = (float)Bm[d][j];
}

// ============================================================================
// k0u: stage-1 partial reduction of u = w0@w1, c = b0@w1.
//      grid (KCH, 2) x 128 threads.
// ============================================================================
__global__ void __launch_bounds__(128) k0u_part(
    const float* __restrict__ w0, const float* __restrict__ b0,
    const float* __restrict__ w1)
{
    const int j = blockIdx.y * 128 + threadIdx.x;
    const int b = blockIdx.x;
    float uu = 0.f, cc = 0.f;
#pragma unroll
    for (int kk = 0; kk < HDIM / KCH; kk++) {
        int k = b * (HDIM / KCH) + kk;
        float wv = w1[k * HDIM + j];
        uu = fmaf(w0[k], wv, uu);
        cc = fmaf(b0[k], wv, cc);
    }
    g_upart[b * HDIM + j] = uu;
    g_cpart[b * HDIM + j] = cc;
}

// ============================================================================
// kT1: h2 tile (32 rows x 64 cols) + IMMEDIATE w3 projection.
//      H2tile = relu( relu(x*u+c) @ w2[:, j0:j0+64] + b2[j0:] )   (smem)
//      Tpart  = H2tile @ w3[j0:j0+64, :]                          (-> global)
//      Kills the 1MB g_H2 round-trip; kT2 becomes a tiny reducer.
// ============================================================================
__global__ void __launch_bounds__(256) kT1_h2proj(
    const float* __restrict__ b1,
    const float* __restrict__ w2, const float* __restrict__ b2,
    const float* __restrict__ w3, int nrows)
{
    __shared__ float us[HDIM], cs[HDIM];
    __shared__ float xs[32];
    __shared__ float As[16][36];     // stride 144B (16B-aligned)
    __shared__ float Bs[16][64];
    __shared__ float H2t[32][66];    // stride 264B (8B-aligned for float2)

    const int grp = blockIdx.x;
    const int jy  = blockIdx.y;
    const int i0 = grp * 32;
    const int j0 = jy * 64;
    const int tid = threadIdx.x;

    {
        float uu = 0.f, cc = 0.f;
#pragma unroll
        for (int b = 0; b < KCH; b++) {
            uu += g_upart[b * HDIM + tid];
            cc += g_cpart[b * HDIM + tid];
        }
        us[tid] = uu;
        cs[tid] = cc + b1[tid];
    }
    if (tid < 32)
        xs[tid] = (float)(i0 + tid) * (1.0f / (float)GTAB);
    __syncthreads();

    const int tx = tid & 31;       // 32 col groups of 2
    const int ty = tid >> 5;       // 8 row groups of 4

    float acc[4][2];
#pragma unroll
    for (int m = 0; m < 4; m++) { acc[m][0] = 0.f; acc[m][1] = 0.f; }

    for (int k0 = 0; k0 < HDIM; k0 += 16) {
#pragma unroll
        for (int s = 0; s < 2; s++) {           // As: 512 elems
            int e = tid + s * 256;
            int kk = e >> 5, ii = e & 31;
            As[kk][ii] = fmaxf(fmaf(xs[ii], us[k0 + kk], cs[k0 + kk]), 0.f);
        }
#pragma unroll
        for (int s = 0; s < 4; s++) {           // Bs: 1024 elems
            int e = tid + s * 256;
            int kk = e >> 6, jj = e & 63;
            Bs[kk][jj] = w2[(k0 + kk) * HDIM + j0 + jj];
        }
        __syncthreads();
#pragma unroll
        for (int kk = 0; kk < 16; kk++) {
            float4 a4 = *reinterpret_cast<const float4*>(&As[kk][ty * 4]);
            float2 bv = *reinterpret_cast<const float2*>(&Bs[kk][tx * 2]);
            float a[4] = {a4.x, a4.y, a4.z, a4.w};
#pragma unroll
            for (int m = 0; m < 4; m++) {
                acc[m][0] = fmaf(a[m], bv.x, acc[m][0]);
                acc[m][1] = fmaf(a[m], bv.y, acc[m][1]);
            }
        }
        __syncthreads();
    }

    // H2 tile -> smem (relu applied)
    float bb0 = b2[j0 + tx * 2];
    float bb1 = b2[j0 + tx * 2 + 1];
#pragma unroll
    for (int m = 0; m < 4; m++) {
        float2 v;
        v.x = fmaxf(acc[m][0] + bb0, 0.f);
        v.y = fmaxf(acc[m][1] + bb1, 0.f);
        *reinterpret_cast<float2*>(&H2t[ty * 4 + m][tx * 2]) = v;
    }
    __syncthreads();

    // Tpart[i][d] = sum_jj H2t[i][jj] * w3[(j0+jj)*DTH + d]
    {
        const int i = tid & 31;
        const int dg = tid >> 5;             // 8 groups x 4 d (last group: d=28..31, 31 valid)
        const int d0 = dg * 4;
        float a4[4] = {0.f, 0.f, 0.f, 0.f};
#pragma unroll 8
        for (int jj = 0; jj < 64; jj++) {
            float h = H2t[i][jj];
            const float* w3r = &w3[(j0 + jj) * DTH + d0];
            a4[0] = fmaf(h, __ldg(&w3r[0]), a4[0]);
            if (d0 + 1 < DTH) a4[1] = fmaf(h, __ldg(&w3r[1]), a4[1]);
            if (d0 + 2 < DTH) a4[2] = fmaf(h, __ldg(&w3r[2]), a4[2]);
            if (d0 + 3 < DTH) a4[3] = fmaf(h, __ldg(&w3r[3]), a4[3]);
        }
        float* tp = &g_Tpart[((grp * 4 + jy) * 32 + i) * DTH + d0];
        tp[0] = a4[0];
        if (d0 + 1 < DTH) tp[1] = a4[1];
        if (d0 + 2 < DTH) tp[2] = a4[2];
        if (d0 + 3 < DTH) tp[3] = a4[3];
    }
}

// ============================================================================
// kT2: tiny reducer.  T = sum_jy Tpart (+b3);  A = T @ B^T -> g_Atab.
// ============================================================================
__global__ void __launch_bounds__(256) kT2_atab(
    const BParam Bp, const float* __restrict__ b3, int nrows)
{
    __shared__ float Ts[32][33];     // [d][i]
    __shared__ float Bb[DTH][64];

    const int grp = blockIdx.x;
    const int i0 = grp * 32;
    const int tid = threadIdx.x;

    // sum 4 parts in fixed order (deterministic)
    for (int e = tid; e < 32 * DTH; e += 256) {
        int i = e / DTH, d = e % DTH;
        const float* tp = &g_Tpart[((grp * 4) * 32 + i) * DTH + d];
        float s = tp[0] + tp[32 * DTH] + tp[2 * 32 * DTH] + tp[3 * 32 * DTH];
        Ts[d][i] = s + b3[d];
    }
    for (int e = tid; e < DTH * 64; e += 256)
        Bb[e >> 6][e & 63] = Bp.B[e];
    __syncthreads();

    // A = T @ B^T
    const int j = tid & 63;
    const int ig = tid >> 6;             // 0..3
    float acc8[8];
#pragma unroll
    for (int m = 0; m < 8; m++) acc8[m] = 0.f;
#pragma unroll
    for (int d = 0; d < DTH; d++) {
        float bv = Bb[d][j];
#pragma unroll
        for (int m = 0; m < 8; m++)
            acc8[m] = fmaf(Ts[d][ig + m * 4], bv, acc8[m]);
    }
#pragma unroll
    for (int m = 0; m < 8; m++) {
        int row = i0 + ig + m * 4;
        if (row < nrows)
            g_Atab[row * 64 + j] = acc8[m];
    }
}

// ============================================================================
// k3: CPAB integration, 1 point/thread, fast intrinsics throughout
//     (incl. e=b/a — table error dominates budget ~150x). Exact fixpoint
//     early-exit; redundant clamps removed.
// ============================================================================
__global__ void __launch_bounds__(256) k3_integrate(const float* __restrict__ x,
                                                    float* __restrict__ out, int n)
{
    const int ip = blockIdx.x * 256 + threadIdx.x;
    if (ip >= n) return;

    float2 xv = *reinterpret_cast<const float2*>(&x[2 * ip]);
    float x1 = fminf(fmaxf(xv.y, EPSF), 1.0f - EPSF);
    float f = x1 * (float)GTAB;
    int r = (int)f;                                  // in [0, GTAB-1] by range
    float fr = f - (float)r;
    const float2* row0 = reinterpret_cast<const float2*>(&g_Atab[r * 64]);
    const float2* row1 = reinterpret_cast<const float2*>(&g_Atab[(r + 1) * 64]);

    float xc = fminf(fmaxf(xv.x, EPSF), 1.0f - EPSF);
    float t = 1.0f;
    float S = 0.0f;
    const float inv = 1.0f / (float)NCELL;
    const float INF = __int_as_float(0x7f800000);

#pragma unroll 1
    for (int it = 0; it < NCELL + 2; it++) {
        int c = (int)(xc * (float)NCELL);            // in [0, 31] by range
        float2 p0 = __ldg(&row0[c]);
        float2 p1 = __ldg(&row1[c]);
        float a = fmaf(fr, p1.x - p0.x, p0.x);
        float b = fmaf(fr, p1.y - p0.y, p0.y);
        float v = a * xc + b;
        float xbnd = ((v >= 0.f) ? (float)(c + 1) : (float)c) * inv;
        bool  small_a = fabsf(a) < TINYF;
        float safe_a = small_a ? 1.0f : a;
        float e = __fdividef(b, safe_a);
        float denom = xc + e;
        float safe_denom = (fabsf(denom) < TINYF) ? ((denom >= 0.f) ? TINYF : -TINYF) : denom;
        float ratio = __fdividef(xbnd + e, safe_denom);
        float thit_exp = __fdividef(__logf(fmaxf(ratio, TINYF)), safe_a);
        float safe_b = (fabsf(b) < TINYF) ? TINYF : b;
        float thit_lin = __fdividef(xbnd - xc, safe_b);
        float thit = small_a ? thit_lin : ((ratio > TINYF) ? thit_exp : INF);
        thit = (thit <= 0.f) ? INF : thit;
        float dt = fminf(thit, t);
        bool cross = (thit <= t);
        float x_exp = (xc + e) * __expf(a * dt) - e;
        float x_lin = xc + b * dt;
        float xn = small_a ? x_lin : x_exp;
        float nudge = (v >= 0.f) ? 1e-7f : -1e-7f;
        xn = cross ? (xbnd + nudge) : xn;
        xn = fminf(fmaxf(xn, EPSF), 1.0f - EPSF);
        S += a * dt;
        t = t - dt;
        bool done = (dt == 0.0f) && (xn == xc);     // exact fixpoint
        xc = xn;
        if (__all_sync(0xffffffffu, done)) break;
    }

    float2 z; z.x = xc; z.y = x1;
    *reinterpret_cast<float2*>(&out[2 * ip]) = z;
    float2 g; g.x = S; g.y = 0.0f;
    *reinterpret_cast<float2*>(&out[2 * n + 2 * ip]) = g;
}

// ============================================================================
static BParam s_Bp;               // persists across graph replays

extern "C" void kernel_launch(void* const* d_in, const int* in_sizes, int n_in,
                              void* d_out, int out_size)
{
    const float* x  = (const float*)d_in[0];
    const float* w0 = (const float*)d_in[1];
    const float* b0 = (const float*)d_in[2];
    const float* w1 = (const float*)d_in[3];
    const float* b1 = (const float*)d_in[4];
    const float* w2 = (const float*)d_in[5];
    const float* b2 = (const float*)d_in[6];
    const float* w3 = (const float*)d_in[7];
    const float* b3 = (const float*)d_in[8];
    float* out = (float*)d_out;

    int n = in_sizes[0] / 2;
    const int nrows = GTAB + 1;

    compute_basis_host(s_Bp.B);     // input-independent, deterministic

    dim3 g0(KCH, 2);
    k0u_part<<<g0, 128>>>(w0, b0, w1);

    dim3 g1(NGRP, 4);
    kT1_h2proj<<<g1, 256>>>(b1, w2, b2, w3, nrows);

    kT2_atab<<<NGRP, 256>>>(s_Bp, b3, nrows);

    k3_integrate<<<(n + 255) / 256, 256>>>(x, out, n);
}